// round 3
// baseline (speedup 1.0000x reference)
#include <cuda_runtime.h>
#include <math.h>
#include <stdint.h>

#define NS 19200   // T*H*W
#define TT 12
#define HH 40
#define WW 40
#define CC 128

__device__ float g_xn[NS * CC];
__device__ float g_qkv[NS * 3 * CC];
__device__ float g_att[NS * CC];

__device__ __forceinline__ void mma_tf32(float* c, const uint32_t* a, const uint32_t* b) {
    asm volatile(
        "mma.sync.aligned.m16n8k8.row.col.f32.tf32.tf32.f32 "
        "{%0,%1,%2,%3}, {%4,%5,%6,%7}, {%8,%9}, {%0,%1,%2,%3};\n"
        : "+f"(c[0]), "+f"(c[1]), "+f"(c[2]), "+f"(c[3])
        : "r"(a[0]), "r"(a[1]), "r"(a[2]), "r"(a[3]), "r"(b[0]), "r"(b[1]));
}

// ---------------------------------------------------------------------------
// Kernel 1: channel RMS norm in (C,T,H,W) layout, float4 over s.
// ---------------------------------------------------------------------------
__global__ void norm_kernel(const float* __restrict__ x,
                            const float* __restrict__ gamma) {
    int s4 = (blockIdx.x * blockDim.x + threadIdx.x) * 4;
    if (s4 >= NS) return;
    float4 ss = {0.f, 0.f, 0.f, 0.f};
#pragma unroll 8
    for (int c = 0; c < CC; c++) {
        float4 v = *(const float4*)(x + (size_t)c * NS + s4);
        ss.x = fmaf(v.x, v.x, ss.x);
        ss.y = fmaf(v.y, v.y, ss.y);
        ss.z = fmaf(v.z, v.z, ss.z);
        ss.w = fmaf(v.w, v.w, ss.w);
    }
    const float sC = 11.313708498984761f;  // sqrt(128)
    float4 inv;
    inv.x = sC / fmaxf(sqrtf(ss.x), 1e-12f);
    inv.y = sC / fmaxf(sqrtf(ss.y), 1e-12f);
    inv.z = sC / fmaxf(sqrtf(ss.z), 1e-12f);
    inv.w = sC / fmaxf(sqrtf(ss.w), 1e-12f);
#pragma unroll 8
    for (int c = 0; c < CC; c++) {
        float g = __ldg(&gamma[c]);
        float4 v = *(const float4*)(x + (size_t)c * NS + s4);
        v.x *= inv.x * g; v.y *= inv.y * g; v.z *= inv.z * g; v.w *= inv.w * g;
        *(float4*)(g_xn + (size_t)c * NS + s4) = v;
    }
}

// ---------------------------------------------------------------------------
// Kernel 2/4: tf32 GEMM, 128x128 CTA tile, 8 warps (64x32 each), BK=32,
// register double-buffered global loads, raw fp32 bits fed as tf32.
// ---------------------------------------------------------------------------
#define LDT 136

template <int NN, int MODE>
__global__ void __launch_bounds__(256, 2)
gemm_tf32(const float* __restrict__ Bw, const float* __restrict__ bias,
          const float* __restrict__ resid, float* __restrict__ outArg) {
    __shared__ uint32_t As[32 * LDT];  // [k][m]
    __shared__ uint32_t Bs[32 * LDT];  // [k][n]

    const float* __restrict__ A = (MODE == 0) ? g_xn : g_att;
    float* __restrict__ Cout    = (MODE == 0) ? g_qkv : outArg;

    int tid = threadIdx.x;
    int lane = tid & 31;
    int warp = tid >> 5;
    int wm = warp & 1;
    int wn = warp >> 1;
    int g = lane >> 2, tg = lane & 3;

    float acc[4][4][4];
#pragma unroll
    for (int i = 0; i < 4; i++)
#pragma unroll
        for (int j = 0; j < 4; j++)
#pragma unroll
            for (int e = 0; e < 4; e++) acc[i][j][e] = 0.f;

    int r = tid >> 1;
    int c0 = (tid & 1) * 16;
    const float* Ag = A  + (size_t)(blockIdx.y * 128 + r) * CC + c0;
    const float* Bg = Bw + (size_t)(blockIdx.x * 128 + r) * CC + c0;

    float4 pa[4], pb[4];
#pragma unroll
    for (int j = 0; j < 4; j++) {
        pa[j] = *(const float4*)(Ag + j * 4);
        pb[j] = *(const float4*)(Bg + j * 4);
    }

#pragma unroll
    for (int k0 = 0; k0 < 128; k0 += 32) {
#pragma unroll
        for (int j = 0; j < 4; j++) {
            int kk = c0 + j * 4;
            As[(kk + 0) * LDT + r] = __float_as_uint(pa[j].x);
            As[(kk + 1) * LDT + r] = __float_as_uint(pa[j].y);
            As[(kk + 2) * LDT + r] = __float_as_uint(pa[j].z);
            As[(kk + 3) * LDT + r] = __float_as_uint(pa[j].w);
            Bs[(kk + 0) * LDT + r] = __float_as_uint(pb[j].x);
            Bs[(kk + 1) * LDT + r] = __float_as_uint(pb[j].y);
            Bs[(kk + 2) * LDT + r] = __float_as_uint(pb[j].z);
            Bs[(kk + 3) * LDT + r] = __float_as_uint(pb[j].w);
        }
        __syncthreads();
        if (k0 < 96) {  // prefetch next chunk; LDGs overlap the mma below
#pragma unroll
            for (int j = 0; j < 4; j++) {
                pa[j] = *(const float4*)(Ag + k0 + 32 + j * 4);
                pb[j] = *(const float4*)(Bg + k0 + 32 + j * 4);
            }
        }
#pragma unroll
        for (int ks = 0; ks < 4; ks++) {
            int kb = ks * 8;
            uint32_t af[4][4], bf[4][2];
#pragma unroll
            for (int mt = 0; mt < 4; mt++) {
                int m = wm * 64 + mt * 16 + g;
                af[mt][0] = As[(kb + tg    ) * LDT + m];
                af[mt][1] = As[(kb + tg    ) * LDT + m + 8];
                af[mt][2] = As[(kb + tg + 4) * LDT + m];
                af[mt][3] = As[(kb + tg + 4) * LDT + m + 8];
            }
#pragma unroll
            for (int nt = 0; nt < 4; nt++) {
                int n = wn * 32 + nt * 8 + g;
                bf[nt][0] = Bs[(kb + tg    ) * LDT + n];
                bf[nt][1] = Bs[(kb + tg + 4) * LDT + n];
            }
#pragma unroll
            for (int mt = 0; mt < 4; mt++)
#pragma unroll
                for (int nt = 0; nt < 4; nt++)
                    mma_tf32(acc[mt][nt], af[mt], bf[nt]);
        }
        __syncthreads();
    }

#pragma unroll
    for (int nt = 0; nt < 4; nt++) {
        int n = blockIdx.x * 128 + wn * 32 + nt * 8 + 2 * tg;
        float2 bb = *(const float2*)(bias + n);
#pragma unroll
        for (int mt = 0; mt < 4; mt++) {
            int row0 = blockIdx.y * 128 + wm * 64 + mt * 16 + g;
            float2 o0 = { acc[mt][nt][0] + bb.x, acc[mt][nt][1] + bb.y };
            float2 o1 = { acc[mt][nt][2] + bb.x, acc[mt][nt][3] + bb.y };
            if (MODE == 1) {
                float2 r0 = *(const float2*)(resid + (size_t)row0 * NN + n);
                float2 r1 = *(const float2*)(resid + (size_t)(row0 + 8) * NN + n);
                o0.x += r0.x; o0.y += r0.y;
                o1.x += r1.x; o1.y += r1.y;
            }
            *(float2*)(Cout + (size_t)row0 * NN + n) = o0;
            *(float2*)(Cout + (size_t)(row0 + 8) * NN + n) = o1;
        }
    }
}

// ---------------------------------------------------------------------------
// Kernel 3: neighborhood attention, 2t x 2h x 4w = 16 positions per CTA.
// Union neighborhood 4x4x6 = 96 k/v rows staged once in smem.
// Scores: one full 128-dot per thread (no shuffles).
// ---------------------------------------------------------------------------
#define KLD 132
#define A_NPOS 16
#define A_NDOT (A_NPOS * 27)   // 432

__global__ void __launch_bounds__(256)
attn_kernel(const float* __restrict__ rpb) {
    extern __shared__ float sm[];
    float* ksm = sm;                        // 96*KLD
    float* vsm = ksm + 96 * KLD;            // 96*KLD
    float* qsm = vsm + 96 * KLD;            // 16*KLD
    float* sc  = qsm + 16 * KLD;            // 16*32
    float* aw  = sc + 512;                  // 16*32
    int*   sl  = (int*)(aw + 512);          // 16*32

    int tid = threadIdx.x, lane = tid & 31, warp = tid >> 5;
    int w0 = blockIdx.x * 4, h0 = blockIdx.y * 2, t0 = blockIdx.z * 2;

    int tlo = min(max(t0 - 1, 0), TT - 3);
    int hlo = min(max(h0 - 1, 0), HH - 3);
    int wlo = min(max(w0 - 1, 0), WW - 3);

    // bias + slot for all (pos, neighbor) pairs
#pragma unroll
    for (int i = 0; i < 2; i++) {
        int d = tid + i * 256;
        if (d < A_NDOT) {
            int j = d / 27, n = d % 27;
            int pt = t0 + (j >> 3), ph = h0 + ((j >> 2) & 1), pw = w0 + (j & 3);
            int dt = n / 9, dh = (n / 3) % 3, dw = n % 3;
            int stt = min(max(pt - 1, 0), TT - 3);
            int sh  = min(max(ph - 1, 0), HH - 3);
            int sw  = min(max(pw - 1, 0), WW - 3);
            int nt = stt + dt, nh = sh + dh, nw = sw + dw;
            sl[j * 32 + n] = ((nt - tlo) * 4 + (nh - hlo)) * 6 + (nw - wlo);
            int bt = nt - pt + 2, bh = nh - ph + 2, bw = nw - pw + 2;
            sc[j * 32 + n] = __ldg(&rpb[(bt * 5 + bh) * 5 + bw]);
        }
    }

    // q staging (scaled by C^-0.5): warp handles pos warp and warp+8
#pragma unroll
    for (int i = 0; i < 2; i++) {
        int j = warp + i * 8;
        int pt = t0 + (j >> 3), ph = h0 + ((j >> 2) & 1), pw = w0 + (j & 3);
        int p = (pt * HH + ph) * WW + pw;
        float4 q4 = *(const float4*)(g_qkv + (size_t)p * 384 + lane * 4);
        const float s = 0.08838834764831845f;
        q4.x *= s; q4.y *= s; q4.z *= s; q4.w *= s;
        *(float4*)(qsm + j * KLD + lane * 4) = q4;
    }

    // stage union k/v rows
    for (int rowid = warp; rowid < 96; rowid += 8) {
        int dt = rowid / 24, rrem = rowid % 24;
        int dh = rrem / 6, dw = rrem % 6;
        int nt = min(tlo + dt, TT - 1);
        int nh = min(hlo + dh, HH - 1);
        int nw = min(wlo + dw, WW - 1);
        int np = (nt * HH + nh) * WW + nw;
        const float* base = g_qkv + (size_t)np * 384;
        *(float4*)(ksm + rowid * KLD + lane * 4) = *(const float4*)(base + 128 + lane * 4);
        *(float4*)(vsm + rowid * KLD + lane * 4) = *(const float4*)(base + 256 + lane * 4);
    }
    __syncthreads();

    // scores: each thread does full 128-dot for its (pos, neighbor)
#pragma unroll
    for (int i = 0; i < 2; i++) {
        int d = tid + i * 256;
        if (d < A_NDOT) {
            int j = d / 27, n = d % 27;
            const float* qp = qsm + j * KLD;
            const float* kp = ksm + sl[j * 32 + n] * KLD;
            float s = 0.f;
#pragma unroll
            for (int e = 0; e < 32; e++) {
                float4 qv = *(const float4*)(qp + e * 4);
                float4 kv = *(const float4*)(kp + e * 4);
                s = fmaf(qv.x, kv.x, s);
                s = fmaf(qv.y, kv.y, s);
                s = fmaf(qv.z, kv.z, s);
                s = fmaf(qv.w, kv.w, s);
            }
            sc[j * 32 + n] += s;
        }
    }
    __syncthreads();

    // softmax per position (warp handles pos warp, warp+8)
#pragma unroll
    for (int i = 0; i < 2; i++) {
        int j = warp + i * 8;
        float s = (lane < 27) ? sc[j * 32 + lane] : -1e30f;
        float m = s;
#pragma unroll
        for (int o = 16; o; o >>= 1) m = fmaxf(m, __shfl_xor_sync(0xffffffffu, m, o));
        float e = (lane < 27) ? __expf(s - m) : 0.f;
        float den = e;
#pragma unroll
        for (int o = 16; o; o >>= 1) den += __shfl_xor_sync(0xffffffffu, den, o);
        aw[j * 32 + lane] = e / den;
    }
    __syncthreads();

    // out = sum_n a_n * v_n
#pragma unroll
    for (int i = 0; i < 2; i++) {
        int j = warp + i * 8;
        int pt = t0 + (j >> 3), ph = h0 + ((j >> 2) & 1), pw = w0 + (j & 3);
        int p = (pt * HH + ph) * WW + pw;
        float4 acc = {0.f, 0.f, 0.f, 0.f};
#pragma unroll
        for (int n = 0; n < 27; n++) {
            float a = aw[j * 32 + n];
            const float* vp = vsm + sl[j * 32 + n] * KLD;
            float4 v4 = *(const float4*)(vp + lane * 4);
            acc.x = fmaf(a, v4.x, acc.x);
            acc.y = fmaf(a, v4.y, acc.y);
            acc.z = fmaf(a, v4.z, acc.z);
            acc.w = fmaf(a, v4.w, acc.w);
        }
        *(float4*)(g_att + (size_t)p * 128 + lane * 4) = acc;
    }
}

static const int ATTN_SMEM = (96 * KLD * 2 + 16 * KLD + 512 * 3) * 4;  // 115968 B

// ---------------------------------------------------------------------------
extern "C" void kernel_launch(void* const* d_in, const int* in_sizes, int n_in,
                              void* d_out, int out_size) {
    const float* x      = (const float*)d_in[0];
    const float* gamma  = (const float*)d_in[1];
    const float* qkv_w  = (const float*)d_in[2];
    const float* qkv_b  = (const float*)d_in[3];
    const float* rpb    = (const float*)d_in[4];
    const float* proj_w = (const float*)d_in[5];
    const float* proj_b = (const float*)d_in[6];
    float* out = (float*)d_out;

    cudaFuncSetAttribute(attn_kernel, cudaFuncAttributeMaxDynamicSharedMemorySize, ATTN_SMEM);

    norm_kernel<<<(NS / 4 + 255) / 256, 256>>>(x, gamma);
    gemm_tf32<384, 0><<<dim3(3, NS / 128), 256>>>(qkv_w, qkv_b, nullptr, nullptr);
    attn_kernel<<<dim3(WW / 4, HH / 2, TT / 2), 256, ATTN_SMEM>>>(rpb);
    gemm_tf32<128, 1><<<dim3(1, NS / 128), 256>>>(proj_w, proj_b, x, out);
}

// round 4
// speedup vs baseline: 1.1299x; 1.1299x over previous
#include <cuda_runtime.h>
#include <math.h>
#include <stdint.h>

#define NS 19200   // T*H*W
#define TT 12
#define HH 40
#define WW 40
#define CC 128

__device__ float g_xn[NS * CC];
__device__ float g_qkv[NS * 3 * CC];
__device__ float g_att[NS * CC];

__device__ __forceinline__ void mma_tf32(float* c, const uint32_t* a, const uint32_t* b) {
    asm volatile(
        "mma.sync.aligned.m16n8k8.row.col.f32.tf32.tf32.f32 "
        "{%0,%1,%2,%3}, {%4,%5,%6,%7}, {%8,%9}, {%0,%1,%2,%3};\n"
        : "+f"(c[0]), "+f"(c[1]), "+f"(c[2]), "+f"(c[3])
        : "r"(a[0]), "r"(a[1]), "r"(a[2]), "r"(a[3]), "r"(b[0]), "r"(b[1]));
}

__device__ __forceinline__ void cp16(uint32_t dst, const void* src) {
    asm volatile("cp.async.ca.shared.global [%0], [%1], 16;" :: "r"(dst), "l"(src));
}
__device__ __forceinline__ void cp_commit() {
    asm volatile("cp.async.commit_group;");
}
template <int N>
__device__ __forceinline__ void cp_wait() {
    asm volatile("cp.async.wait_group %0;" :: "n"(N));
}

// ---------------------------------------------------------------------------
// Kernel 1: channel RMS norm in (C,T,H,W) layout, float4 over s.
// ---------------------------------------------------------------------------
__global__ void norm_kernel(const float* __restrict__ x,
                            const float* __restrict__ gamma) {
    int s4 = (blockIdx.x * blockDim.x + threadIdx.x) * 4;
    if (s4 >= NS) return;
    float4 ss = {0.f, 0.f, 0.f, 0.f};
#pragma unroll 8
    for (int c = 0; c < CC; c++) {
        float4 v = *(const float4*)(x + (size_t)c * NS + s4);
        ss.x = fmaf(v.x, v.x, ss.x);
        ss.y = fmaf(v.y, v.y, ss.y);
        ss.z = fmaf(v.z, v.z, ss.z);
        ss.w = fmaf(v.w, v.w, ss.w);
    }
    const float sC = 11.313708498984761f;  // sqrt(128)
    float4 inv;
    inv.x = sC / fmaxf(sqrtf(ss.x), 1e-12f);
    inv.y = sC / fmaxf(sqrtf(ss.y), 1e-12f);
    inv.z = sC / fmaxf(sqrtf(ss.z), 1e-12f);
    inv.w = sC / fmaxf(sqrtf(ss.w), 1e-12f);
#pragma unroll 8
    for (int c = 0; c < CC; c++) {
        float g = __ldg(&gamma[c]);
        float4 v = *(const float4*)(x + (size_t)c * NS + s4);
        v.x *= inv.x * g; v.y *= inv.y * g; v.z *= inv.z * g; v.w *= inv.w * g;
        *(float4*)(g_xn + (size_t)c * NS + s4) = v;
    }
}

// ---------------------------------------------------------------------------
// Kernel 2/4: tf32 GEMM. C[M,NN] = A[M,128]@B[NN,128]^T + bias (+resid MODE 1)
// Tile 64(M)x128(N), BK=32, 256 thr = 8 warps (2M x 4N), warp tile 32x32.
// cp.async double-buffered smem, [row][k] layout pad 36 (conflict-free frags).
// ---------------------------------------------------------------------------
#define LDK 36
#define A_ST (64 * LDK)    // one A stage (floats)
#define B_ST (128 * LDK)   // one B stage
#define GSMEM ((2 * A_ST + 2 * B_ST) * 4)  // 55296 B

template <int NN, int MODE>
__global__ void __launch_bounds__(256, 2)
gemm_tf32(const float* __restrict__ Bw, const float* __restrict__ bias,
          const float* __restrict__ resid, float* __restrict__ outArg) {
    extern __shared__ float smem[];
    float* As = smem;                 // [2][64][LDK]
    float* Bs = smem + 2 * A_ST;      // [2][128][LDK]
    uint32_t sb = (uint32_t)__cvta_generic_to_shared(smem);
    uint32_t sbB = sb + 2 * A_ST * 4;

    const float* __restrict__ A = (MODE == 0) ? g_xn : g_att;
    float* __restrict__ Cout    = (MODE == 0) ? g_qkv : outArg;

    int tid = threadIdx.x;
    int lane = tid & 31;
    int warp = tid >> 5;
    int wm = warp & 1;    // 2 warps in M (32 rows each)
    int wn = warp >> 1;   // 4 warps in N (32 cols each)
    int g = lane >> 2, tg = lane & 3;

    const float* Abase = A  + (size_t)blockIdx.y * 64 * CC;
    const float* Bbase = Bw + (size_t)blockIdx.x * 128 * CC;

    // stage loader: A = 512 chunks (2/thr), B = 1024 chunks (4/thr)
    auto load_stage = [&](int k0, int buf) {
#pragma unroll
        for (int i = 0; i < 2; i++) {
            int ch = tid + i * 256;
            int r = ch >> 3, c = (ch & 7) * 4;
            cp16(sb + (buf * A_ST + r * LDK + c) * 4, Abase + r * CC + k0 + c);
        }
#pragma unroll
        for (int i = 0; i < 4; i++) {
            int ch = tid + i * 256;
            int r = ch >> 3, c = (ch & 7) * 4;
            cp16(sbB + (buf * B_ST + r * LDK + c) * 4, Bbase + r * CC + k0 + c);
        }
        cp_commit();
    };

    float acc[2][4][4];
#pragma unroll
    for (int i = 0; i < 2; i++)
#pragma unroll
        for (int j = 0; j < 4; j++)
#pragma unroll
            for (int e = 0; e < 4; e++) acc[i][j][e] = 0.f;

    load_stage(0, 0);

#pragma unroll
    for (int k0 = 0; k0 < 4; k0++) {
        if (k0 < 3) load_stage((k0 + 1) * 32, (k0 + 1) & 1);
        if (k0 < 3) cp_wait<1>(); else cp_wait<0>();
        __syncthreads();

        const uint32_t* Ab = (const uint32_t*)(As + (k0 & 1) * A_ST);
        const uint32_t* Bb = (const uint32_t*)(Bs + (k0 & 1) * B_ST);
#pragma unroll
        for (int ks = 0; ks < 4; ks++) {
            int kb = ks * 8;
            uint32_t af[2][4], bf[4][2];
#pragma unroll
            for (int mt = 0; mt < 2; mt++) {
                int m = wm * 32 + mt * 16 + g;
                af[mt][0] = Ab[m * LDK + kb + tg];
                af[mt][1] = Ab[(m + 8) * LDK + kb + tg];
                af[mt][2] = Ab[m * LDK + kb + tg + 4];
                af[mt][3] = Ab[(m + 8) * LDK + kb + tg + 4];
            }
#pragma unroll
            for (int nt = 0; nt < 4; nt++) {
                int n = wn * 32 + nt * 8 + g;
                bf[nt][0] = Bb[n * LDK + kb + tg];
                bf[nt][1] = Bb[n * LDK + kb + tg + 4];
            }
#pragma unroll
            for (int mt = 0; mt < 2; mt++)
#pragma unroll
                for (int nt = 0; nt < 4; nt++)
                    mma_tf32(acc[mt][nt], af[mt], bf[nt]);
        }
        __syncthreads();
    }

#pragma unroll
    for (int nt = 0; nt < 4; nt++) {
        int n = blockIdx.x * 128 + wn * 32 + nt * 8 + 2 * tg;
        float2 bb = *(const float2*)(bias + n);
#pragma unroll
        for (int mt = 0; mt < 2; mt++) {
            int row0 = blockIdx.y * 64 + wm * 32 + mt * 16 + g;
            float2 o0 = { acc[mt][nt][0] + bb.x, acc[mt][nt][1] + bb.y };
            float2 o1 = { acc[mt][nt][2] + bb.x, acc[mt][nt][3] + bb.y };
            if (MODE == 1) {
                float2 r0 = *(const float2*)(resid + (size_t)row0 * NN + n);
                float2 r1 = *(const float2*)(resid + (size_t)(row0 + 8) * NN + n);
                o0.x += r0.x; o0.y += r0.y;
                o1.x += r1.x; o1.y += r1.y;
            }
            *(float2*)(Cout + (size_t)row0 * NN + n) = o0;
            *(float2*)(Cout + (size_t)(row0 + 8) * NN + n) = o1;
        }
    }
}

// ---------------------------------------------------------------------------
// Kernel 3: neighborhood attention (round-2 form). One CTA (256 thr, 8 warps)
// = 8 positions (1t x 2h x 4w); union 3x4x6 = 72 k/v rows staged in smem.
// ---------------------------------------------------------------------------
#define KLD 132

__global__ void __launch_bounds__(256)
attn_kernel(const float* __restrict__ rpb) {
    extern __shared__ float sm[];
    float* ksm = sm;                      // 72*KLD
    float* vsm = ksm + 72 * KLD;          // 72*KLD
    float* qsm = vsm + 72 * KLD;          // 8*KLD
    float* sc  = qsm + 8 * KLD;           // 8*32
    float* aw  = sc + 256;                // 8*32
    int*   sl  = (int*)(aw + 256);        // 8*32

    int tid = threadIdx.x, lane = tid & 31, warp = tid >> 5;
    int w0 = blockIdx.x * 4, h0 = blockIdx.y * 2, t = blockIdx.z;

    int st  = min(max(t  - 1, 0), TT - 3);
    int hlo = min(max(h0 - 1, 0), HH - 3);
    int wlo = min(max(w0 - 1, 0), WW - 3);

    int ph = h0 + (warp >> 2), pw = w0 + (warp & 3);
    int p  = (t * HH + ph) * WW + pw;

    if (lane < 27) {
        int dt = lane / 9, dh = (lane / 3) % 3, dw = lane % 3;
        int sh = min(max(ph - 1, 0), HH - 3);
        int sw = min(max(pw - 1, 0), WW - 3);
        int nt = st + dt, nh = sh + dh, nw = sw + dw;
        sl[warp * 32 + lane] = (dt * 4 + (nh - hlo)) * 6 + (nw - wlo);
        int bt = nt - t + 2, bh = nh - ph + 2, bw = nw - pw + 2;
        sc[warp * 32 + lane] = __ldg(&rpb[(bt * 5 + bh) * 5 + bw]);
    }

    {
        float4 q4 = *(const float4*)(g_qkv + (size_t)p * 384 + lane * 4);
        const float s = 0.08838834764831845f;
        q4.x *= s; q4.y *= s; q4.z *= s; q4.w *= s;
        *(float4*)(qsm + warp * KLD + lane * 4) = q4;
    }

    for (int rowid = warp; rowid < 72; rowid += 8) {
        int dt = rowid / 24, rrem = rowid % 24;
        int dh = rrem / 6, dw = rrem % 6;
        int nh = min(hlo + dh, HH - 1);
        int nw = min(wlo + dw, WW - 1);
        int np = ((st + dt) * HH + nh) * WW + nw;
        const float* base = g_qkv + (size_t)np * 384;
        *(float4*)(ksm + rowid * KLD + lane * 4) = *(const float4*)(base + 128 + lane * 4);
        *(float4*)(vsm + rowid * KLD + lane * 4) = *(const float4*)(base + 256 + lane * 4);
    }
    __syncthreads();

    {
        float4 q4 = *(const float4*)(qsm + warp * KLD + lane * 4);
#pragma unroll
        for (int n = 0; n < 27; n++) {
            int slot = sl[warp * 32 + n];
            float4 k4 = *(const float4*)(ksm + slot * KLD + lane * 4);
            float d = q4.x * k4.x + q4.y * k4.y + q4.z * k4.z + q4.w * k4.w;
#pragma unroll
            for (int o = 16; o; o >>= 1) d += __shfl_xor_sync(0xffffffffu, d, o);
            if (lane == 0) sc[warp * 32 + n] += d;
        }
    }
    __syncwarp();

    {
        float s = (lane < 27) ? sc[warp * 32 + lane] : -1e30f;
        float m = s;
#pragma unroll
        for (int o = 16; o; o >>= 1) m = fmaxf(m, __shfl_xor_sync(0xffffffffu, m, o));
        float e = (lane < 27) ? __expf(s - m) : 0.f;
        float den = e;
#pragma unroll
        for (int o = 16; o; o >>= 1) den += __shfl_xor_sync(0xffffffffu, den, o);
        aw[warp * 32 + lane] = e / den;
    }
    __syncwarp();

    {
        float4 acc = {0.f, 0.f, 0.f, 0.f};
#pragma unroll
        for (int n = 0; n < 27; n++) {
            float a = aw[warp * 32 + n];
            int slot = sl[warp * 32 + n];
            float4 v4 = *(const float4*)(vsm + slot * KLD + lane * 4);
            acc.x = fmaf(a, v4.x, acc.x);
            acc.y = fmaf(a, v4.y, acc.y);
            acc.z = fmaf(a, v4.z, acc.z);
            acc.w = fmaf(a, v4.w, acc.w);
        }
        *(float4*)(g_att + (size_t)p * 128 + lane * 4) = acc;
    }
}

static const int ATTN_SMEM = (72 * KLD * 2 + 8 * KLD + 256 + 256 + 256) * 4;  // 83328 B

// ---------------------------------------------------------------------------
extern "C" void kernel_launch(void* const* d_in, const int* in_sizes, int n_in,
                              void* d_out, int out_size) {
    const float* x      = (const float*)d_in[0];
    const float* gamma  = (const float*)d_in[1];
    const float* qkv_w  = (const float*)d_in[2];
    const float* qkv_b  = (const float*)d_in[3];
    const float* rpb    = (const float*)d_in[4];
    const float* proj_w = (const float*)d_in[5];
    const float* proj_b = (const float*)d_in[6];
    float* out = (float*)d_out;

    cudaFuncSetAttribute(attn_kernel, cudaFuncAttributeMaxDynamicSharedMemorySize, ATTN_SMEM);
    cudaFuncSetAttribute(gemm_tf32<384, 0>, cudaFuncAttributeMaxDynamicSharedMemorySize, GSMEM);
    cudaFuncSetAttribute(gemm_tf32<128, 1>, cudaFuncAttributeMaxDynamicSharedMemorySize, GSMEM);

    norm_kernel<<<(NS / 4 + 255) / 256, 256>>>(x, gamma);
    gemm_tf32<384, 0><<<dim3(3, NS / 64), 256, GSMEM>>>(qkv_w, qkv_b, nullptr, nullptr);
    attn_kernel<<<dim3(WW / 4, HH / 2, TT), 256, ATTN_SMEM>>>(rpb);
    gemm_tf32<128, 1><<<dim3(1, NS / 64), 256, GSMEM>>>(proj_w, proj_b, x, out);
}

// round 6
// speedup vs baseline: 1.2148x; 1.0751x over previous
#include <cuda_runtime.h>
#include <math.h>
#include <stdint.h>

#define NS 19200   // T*H*W
#define TT 12
#define HH 40
#define WW 40
#define CC 128

__device__ float g_xn[NS * CC];
__device__ float g_qkv[NS * 3 * CC];
__device__ float g_att[NS * CC];

__device__ __forceinline__ void mma_bf16(float* c, const uint32_t* a, const uint32_t* b) {
    asm volatile(
        "mma.sync.aligned.m16n8k16.row.col.f32.bf16.bf16.f32 "
        "{%0,%1,%2,%3}, {%4,%5,%6,%7}, {%8,%9}, {%0,%1,%2,%3};\n"
        : "+f"(c[0]), "+f"(c[1]), "+f"(c[2]), "+f"(c[3])
        : "r"(a[0]), "r"(a[1]), "r"(a[2]), "r"(a[3]), "r"(b[0]), "r"(b[1]));
}

// pack two fp32 -> bf16x2 (lo = x, hi = y)
__device__ __forceinline__ uint32_t pack_bf16(float x, float y) {
    uint32_t r;
    asm("cvt.rn.bf16x2.f32 %0, %1, %2;" : "=r"(r) : "f"(y), "f"(x));
    return r;
}

// ---------------------------------------------------------------------------
// Kernel 1: channel RMS norm in (C,T,H,W) layout, float4 over s.
// ---------------------------------------------------------------------------
__global__ void norm_kernel(const float* __restrict__ x,
                            const float* __restrict__ gamma) {
    int s4 = (blockIdx.x * blockDim.x + threadIdx.x) * 4;
    if (s4 >= NS) return;
    float4 ss = {0.f, 0.f, 0.f, 0.f};
#pragma unroll 8
    for (int c = 0; c < CC; c++) {
        float4 v = *(const float4*)(x + (size_t)c * NS + s4);
        ss.x = fmaf(v.x, v.x, ss.x);
        ss.y = fmaf(v.y, v.y, ss.y);
        ss.z = fmaf(v.z, v.z, ss.z);
        ss.w = fmaf(v.w, v.w, ss.w);
    }
    const float sC = 11.313708498984761f;  // sqrt(128)
    float4 inv;
    inv.x = sC / fmaxf(sqrtf(ss.x), 1e-12f);
    inv.y = sC / fmaxf(sqrtf(ss.y), 1e-12f);
    inv.z = sC / fmaxf(sqrtf(ss.z), 1e-12f);
    inv.w = sC / fmaxf(sqrtf(ss.w), 1e-12f);
#pragma unroll 8
    for (int c = 0; c < CC; c++) {
        float g = __ldg(&gamma[c]);
        float4 v = *(const float4*)(x + (size_t)c * NS + s4);
        v.x *= inv.x * g; v.y *= inv.y * g; v.z *= inv.z * g; v.w *= inv.w * g;
        *(float4*)(g_xn + (size_t)c * NS + s4) = v;
    }
}

// ---------------------------------------------------------------------------
// Kernel 2/4: bf16 GEMM, single-stage smem (full K=128 resident), one sync.
// C[M,NN] = A[M,128]@B[NN,128]^T + bias (+resid MODE 1).
// Tile 64(M)x128(N), 256 thr = 8 warps (2M x 4N), warp tile 32x32,
// 8 k-steps of mma.m16n8k16. smem u32(bf16x2) rows padded to 68 -> frag
// LDS bank = lane (conflict-free).
// ---------------------------------------------------------------------------
#define LDU 68                      // u32 per row (64 data + 4 pad)
#define A_U (64 * LDU)              // 4352 u32
#define B_U (128 * LDU)             // 8704 u32
#define GSMEM ((A_U + B_U) * 4)     // 52224 B
static_assert(GSMEM <= 227 * 1024, "gemm smem exceeds sm_100a limit");

template <int NN, int MODE>
__global__ void __launch_bounds__(256, 2)
gemm_bf16(const float* __restrict__ Bw, const float* __restrict__ bias,
          const float* __restrict__ resid, float* __restrict__ outArg) {
    extern __shared__ uint32_t su[];
    uint32_t* As = su;          // [64][LDU]
    uint32_t* Bs = su + A_U;    // [128][LDU]

    const float* __restrict__ A = (MODE == 0) ? g_xn : g_att;
    float* __restrict__ Cout    = (MODE == 0) ? g_qkv : outArg;

    int tid = threadIdx.x;
    int lane = tid & 31;
    int warp = tid >> 5;
    int wm = warp & 1;    // 2 warps in M (32 rows)
    int wn = warp >> 1;   // 4 warps in N (32 cols)
    int g = lane >> 2, tg = lane & 3;

    const float* Abase = A  + (size_t)blockIdx.y * 64 * CC;
    const float* Bbase = Bw + (size_t)blockIdx.x * 128 * CC;

    // Stage A: 64x128 fp32 = 2048 float4, 8 per thread
#pragma unroll
    for (int i = 0; i < 8; i++) {
        int id = tid + i * 256;
        int r = id >> 5, c4 = (id & 31) << 2;
        float4 v = *(const float4*)(Abase + (size_t)r * CC + c4);
        As[r * LDU + (c4 >> 1)]     = pack_bf16(v.x, v.y);
        As[r * LDU + (c4 >> 1) + 1] = pack_bf16(v.z, v.w);
    }
    // Stage B: 128x128 fp32 = 4096 float4, 16 per thread
#pragma unroll
    for (int i = 0; i < 16; i++) {
        int id = tid + i * 256;
        int r = id >> 5, c4 = (id & 31) << 2;
        float4 v = *(const float4*)(Bbase + (size_t)r * CC + c4);
        Bs[r * LDU + (c4 >> 1)]     = pack_bf16(v.x, v.y);
        Bs[r * LDU + (c4 >> 1) + 1] = pack_bf16(v.z, v.w);
    }
    __syncthreads();   // the only barrier

    float acc[2][4][4];
#pragma unroll
    for (int i = 0; i < 2; i++)
#pragma unroll
        for (int j = 0; j < 4; j++)
#pragma unroll
            for (int e = 0; e < 4; e++) acc[i][j][e] = 0.f;

#pragma unroll
    for (int ks = 0; ks < 8; ks++) {        // k16 steps
        int kb = ks * 8;                    // u32 offset within row
        uint32_t af[2][4], bf[4][2];
#pragma unroll
        for (int mt = 0; mt < 2; mt++) {
            int m = wm * 32 + mt * 16 + g;
            af[mt][0] = As[m * LDU + kb + tg];
            af[mt][1] = As[(m + 8) * LDU + kb + tg];
            af[mt][2] = As[m * LDU + kb + tg + 4];
            af[mt][3] = As[(m + 8) * LDU + kb + tg + 4];
        }
#pragma unroll
        for (int nt = 0; nt < 4; nt++) {
            int n = wn * 32 + nt * 8 + g;
            bf[nt][0] = Bs[n * LDU + kb + tg];
            bf[nt][1] = Bs[n * LDU + kb + tg + 4];
        }
#pragma unroll
        for (int mt = 0; mt < 2; mt++)
#pragma unroll
            for (int nt = 0; nt < 4; nt++)
                mma_bf16(acc[mt][nt], af[mt], bf[nt]);
    }

#pragma unroll
    for (int nt = 0; nt < 4; nt++) {
        int n = blockIdx.x * 128 + wn * 32 + nt * 8 + 2 * tg;
        float2 bb = *(const float2*)(bias + n);
#pragma unroll
        for (int mt = 0; mt < 2; mt++) {
            int row0 = blockIdx.y * 64 + wm * 32 + mt * 16 + g;
            float2 o0 = { acc[mt][nt][0] + bb.x, acc[mt][nt][1] + bb.y };
            float2 o1 = { acc[mt][nt][2] + bb.x, acc[mt][nt][3] + bb.y };
            if (MODE == 1) {
                float2 r0 = *(const float2*)(resid + (size_t)row0 * NN + n);
                float2 r1 = *(const float2*)(resid + (size_t)(row0 + 8) * NN + n);
                o0.x += r0.x; o0.y += r0.y;
                o1.x += r1.x; o1.y += r1.y;
            }
            *(float2*)(Cout + (size_t)row0 * NN + n) = o0;
            *(float2*)(Cout + (size_t)(row0 + 8) * NN + n) = o1;
        }
    }
}

// ---------------------------------------------------------------------------
// Kernel 3: neighborhood attention (round-4 form, unchanged). One CTA (256
// thr, 8 warps) = 8 positions (1t x 2h x 4w); union 3x4x6 = 72 k/v rows.
// ---------------------------------------------------------------------------
#define KLD 132

__global__ void __launch_bounds__(256)
attn_kernel(const float* __restrict__ rpb) {
    extern __shared__ float sm[];
    float* ksm = sm;                      // 72*KLD
    float* vsm = ksm + 72 * KLD;          // 72*KLD
    float* qsm = vsm + 72 * KLD;          // 8*KLD
    float* sc  = qsm + 8 * KLD;           // 8*32
    float* aw  = sc + 256;                // 8*32
    int*   sl  = (int*)(aw + 256);        // 8*32

    int tid = threadIdx.x, lane = tid & 31, warp = tid >> 5;
    int w0 = blockIdx.x * 4, h0 = blockIdx.y * 2, t = blockIdx.z;

    int st  = min(max(t  - 1, 0), TT - 3);
    int hlo = min(max(h0 - 1, 0), HH - 3);
    int wlo = min(max(w0 - 1, 0), WW - 3);

    int ph = h0 + (warp >> 2), pw = w0 + (warp & 3);
    int p  = (t * HH + ph) * WW + pw;

    if (lane < 27) {
        int dt = lane / 9, dh = (lane / 3) % 3, dw = lane % 3;
        int sh = min(max(ph - 1, 0), HH - 3);
        int sw = min(max(pw - 1, 0), WW - 3);
        int nt = st + dt, nh = sh + dh, nw = sw + dw;
        sl[warp * 32 + lane] = (dt * 4 + (nh - hlo)) * 6 + (nw - wlo);
        int bt = nt - t + 2, bh = nh - ph + 2, bw = nw - pw + 2;
        sc[warp * 32 + lane] = __ldg(&rpb[(bt * 5 + bh) * 5 + bw]);
    }

    {
        float4 q4 = *(const float4*)(g_qkv + (size_t)p * 384 + lane * 4);
        const float s = 0.08838834764831845f;
        q4.x *= s; q4.y *= s; q4.z *= s; q4.w *= s;
        *(float4*)(qsm + warp * KLD + lane * 4) = q4;
    }

    for (int rowid = warp; rowid < 72; rowid += 8) {
        int dt = rowid / 24, rrem = rowid % 24;
        int dh = rrem / 6, dw = rrem % 6;
        int nh = min(hlo + dh, HH - 1);
        int nw = min(wlo + dw, WW - 1);
        int np = ((st + dt) * HH + nh) * WW + nw;
        const float* base = g_qkv + (size_t)np * 384;
        *(float4*)(ksm + rowid * KLD + lane * 4) = *(const float4*)(base + 128 + lane * 4);
        *(float4*)(vsm + rowid * KLD + lane * 4) = *(const float4*)(base + 256 + lane * 4);
    }
    __syncthreads();

    {
        float4 q4 = *(const float4*)(qsm + warp * KLD + lane * 4);
#pragma unroll
        for (int n = 0; n < 27; n++) {
            int slot = sl[warp * 32 + n];
            float4 k4 = *(const float4*)(ksm + slot * KLD + lane * 4);
            float d = q4.x * k4.x + q4.y * k4.y + q4.z * k4.z + q4.w * k4.w;
#pragma unroll
            for (int o = 16; o; o >>= 1) d += __shfl_xor_sync(0xffffffffu, d, o);
            if (lane == 0) sc[warp * 32 + n] += d;
        }
    }
    __syncwarp();

    {
        float s = (lane < 27) ? sc[warp * 32 + lane] : -1e30f;
        float m = s;
#pragma unroll
        for (int o = 16; o; o >>= 1) m = fmaxf(m, __shfl_xor_sync(0xffffffffu, m, o));
        float e = (lane < 27) ? __expf(s - m) : 0.f;
        float den = e;
#pragma unroll
        for (int o = 16; o; o >>= 1) den += __shfl_xor_sync(0xffffffffu, den, o);
        aw[warp * 32 + lane] = e / den;
    }
    __syncwarp();

    {
        float4 acc = {0.f, 0.f, 0.f, 0.f};
#pragma unroll
        for (int n = 0; n < 27; n++) {
            float a = aw[warp * 32 + n];
            int slot = sl[warp * 32 + n];
            float4 v4 = *(const float4*)(vsm + slot * KLD + lane * 4);
            acc.x = fmaf(a, v4.x, acc.x);
            acc.y = fmaf(a, v4.y, acc.y);
            acc.z = fmaf(a, v4.z, acc.z);
            acc.w = fmaf(a, v4.w, acc.w);
        }
        *(float4*)(g_att + (size_t)p * 128 + lane * 4) = acc;
    }
}

static const int ATTN_SMEM = (72 * KLD * 2 + 8 * KLD + 256 + 256 + 256) * 4;  // 83328 B
static_assert((72 * KLD * 2 + 8 * KLD + 256 + 256 + 256) * 4 <= 227 * 1024, "attn smem");

// ---------------------------------------------------------------------------
extern "C" void kernel_launch(void* const* d_in, const int* in_sizes, int n_in,
                              void* d_out, int out_size) {
    const float* x      = (const float*)d_in[0];
    const float* gamma  = (const float*)d_in[1];
    const float* qkv_w  = (const float*)d_in[2];
    const float* qkv_b  = (const float*)d_in[3];
    const float* rpb    = (const float*)d_in[4];
    const float* proj_w = (const float*)d_in[5];
    const float* proj_b = (const float*)d_in[6];
    float* out = (float*)d_out;

    cudaFuncSetAttribute(attn_kernel, cudaFuncAttributeMaxDynamicSharedMemorySize, ATTN_SMEM);
    cudaFuncSetAttribute(gemm_bf16<384, 0>, cudaFuncAttributeMaxDynamicSharedMemorySize, GSMEM);
    cudaFuncSetAttribute(gemm_bf16<128, 1>, cudaFuncAttributeMaxDynamicSharedMemorySize, GSMEM);

    norm_kernel<<<(NS / 4 + 255) / 256, 256>>>(x, gamma);
    gemm_bf16<384, 0><<<dim3(3, NS / 64), 256, GSMEM>>>(qkv_w, qkv_b, nullptr, nullptr);
    attn_kernel<<<dim3(WW / 4, HH / 2, TT), 256, ATTN_SMEM>>>(rpb);
    gemm_bf16<128, 1><<<dim3(1, NS / 64), 256, GSMEM>>>(proj_w, proj_b, x, out);
}

// round 7
// speedup vs baseline: 1.8053x; 1.4861x over previous
#include <cuda_runtime.h>
#include <cuda_bf16.h>
#include <math.h>
#include <stdint.h>

#define NS 19200   // T*H*W
#define TT 12
#define HH 40
#define WW 40
#define CC 128

// Scratch (device globals)
__device__ float    g_inv[NS];          // per-position inv-norm * sqrt(C)
__device__ float    g_q[NS * 128];      // q rows, pre-scaled by C^-0.5
__device__ uint32_t g_k[NS * 64];       // k rows, bf16x2 packed
__device__ uint32_t g_v[NS * 64];       // v rows, bf16x2 packed
__device__ float    g_att[NS * 128];    // attention output rows

__device__ __forceinline__ void mma_bf16(float* c, const uint32_t* a, const uint32_t* b) {
    asm volatile(
        "mma.sync.aligned.m16n8k16.row.col.f32.bf16.bf16.f32 "
        "{%0,%1,%2,%3}, {%4,%5,%6,%7}, {%8,%9}, {%0,%1,%2,%3};\n"
        : "+f"(c[0]), "+f"(c[1]), "+f"(c[2]), "+f"(c[3])
        : "r"(a[0]), "r"(a[1]), "r"(a[2]), "r"(a[3]), "r"(b[0]), "r"(b[1]));
}

__device__ __forceinline__ uint32_t pack_bf16(float x, float y) {
    uint32_t r;
    asm("cvt.rn.bf16x2.f32 %0, %1, %2;" : "=r"(r) : "f"(y), "f"(x));  // lo=x, hi=y
    return r;
}

// ---------------------------------------------------------------------------
// Kernel 1: per-position inv norm only. inv[s] = sqrt(C)/max(||x[:,s]||,eps)
// ---------------------------------------------------------------------------
__global__ void inv_kernel(const float* __restrict__ x) {
    int s4 = (blockIdx.x * blockDim.x + threadIdx.x) * 4;
    if (s4 >= NS) return;
    float4 ss = {0.f, 0.f, 0.f, 0.f};
#pragma unroll 8
    for (int c = 0; c < CC; c++) {
        float4 v = *(const float4*)(x + (size_t)c * NS + s4);
        ss.x = fmaf(v.x, v.x, ss.x);
        ss.y = fmaf(v.y, v.y, ss.y);
        ss.z = fmaf(v.z, v.z, ss.z);
        ss.w = fmaf(v.w, v.w, ss.w);
    }
    const float sC = 11.313708498984761f;  // sqrt(128)
    float4 inv;
    inv.x = sC / fmaxf(sqrtf(ss.x), 1e-12f);
    inv.y = sC / fmaxf(sqrtf(ss.y), 1e-12f);
    inv.z = sC / fmaxf(sqrtf(ss.z), 1e-12f);
    inv.w = sC / fmaxf(sqrtf(ss.w), 1e-12f);
    *(float4*)(g_inv + s4) = inv;
}

// ---------------------------------------------------------------------------
// GEMM common geometry: tile 64(M)x128(N), 256 thr = 8 warps (2M x 4N),
// warp tile 32x32, full K=128 resident in bf16 smem, one sync.
// ---------------------------------------------------------------------------
#define LDU 68
#define A_U (64 * LDU)
#define B_U (128 * LDU)
#define GSMEM ((A_U + B_U) * 4)     // 52224 B
static_assert(GSMEM <= 227 * 1024, "gemm smem");

// Kernel 2: qkv GEMM with fused norm on A-load and split q/k/v epilogue.
__global__ void __launch_bounds__(256, 2)
gemm_qkv(const float* __restrict__ x, const float* __restrict__ gamma,
         const float* __restrict__ Bw, const float* __restrict__ bias) {
    extern __shared__ uint32_t su[];
    uint32_t* As = su;
    uint32_t* Bs = su + A_U;

    int tid = threadIdx.x;
    int lane = tid & 31;
    int warp = tid >> 5;
    int wm = warp & 1;
    int wn = warp >> 1;
    int g = lane >> 2, tg = lane & 3;
    int bx = blockIdx.x, by = blockIdx.y;

    // Stage A: normalized x, flat rows. row r -> ch = row/150, s = (row%150)*128+c
#pragma unroll
    for (int i = 0; i < 8; i++) {
        int id = tid + i * 256;
        int r = id >> 5, c4 = (id & 31) << 2;
        int row = by * 64 + r;
        int ch = row / 150;
        int s = (row - ch * 150) * 128 + c4;
        float gm = __ldg(&gamma[ch]);
        float4 iv = *(const float4*)(g_inv + s);
        float4 v = *(const float4*)(x + (size_t)row * 128 + c4);
        v.x *= iv.x * gm; v.y *= iv.y * gm; v.z *= iv.z * gm; v.w *= iv.w * gm;
        As[r * LDU + (c4 >> 1)]     = pack_bf16(v.x, v.y);
        As[r * LDU + (c4 >> 1) + 1] = pack_bf16(v.z, v.w);
    }
    // Stage B: qkv_w rows bx*128..+127
    const float* Bbase = Bw + (size_t)bx * 128 * CC;
#pragma unroll
    for (int i = 0; i < 16; i++) {
        int id = tid + i * 256;
        int r = id >> 5, c4 = (id & 31) << 2;
        float4 v = *(const float4*)(Bbase + (size_t)r * CC + c4);
        Bs[r * LDU + (c4 >> 1)]     = pack_bf16(v.x, v.y);
        Bs[r * LDU + (c4 >> 1) + 1] = pack_bf16(v.z, v.w);
    }
    __syncthreads();

    float acc[2][4][4];
#pragma unroll
    for (int i = 0; i < 2; i++)
#pragma unroll
        for (int j = 0; j < 4; j++)
#pragma unroll
            for (int e = 0; e < 4; e++) acc[i][j][e] = 0.f;

#pragma unroll
    for (int ks = 0; ks < 8; ks++) {
        int kb = ks * 8;
        uint32_t af[2][4], bf[4][2];
#pragma unroll
        for (int mt = 0; mt < 2; mt++) {
            int m = wm * 32 + mt * 16 + g;
            af[mt][0] = As[m * LDU + kb + tg];
            af[mt][1] = As[(m + 8) * LDU + kb + tg];
            af[mt][2] = As[m * LDU + kb + tg + 4];
            af[mt][3] = As[(m + 8) * LDU + kb + tg + 4];
        }
#pragma unroll
        for (int nt = 0; nt < 4; nt++) {
            int n = wn * 32 + nt * 8 + g;
            bf[nt][0] = Bs[n * LDU + kb + tg];
            bf[nt][1] = Bs[n * LDU + kb + tg + 4];
        }
#pragma unroll
        for (int mt = 0; mt < 2; mt++)
#pragma unroll
            for (int nt = 0; nt < 4; nt++)
                mma_bf16(acc[mt][nt], af[mt], bf[nt]);
    }

    const float QS = 0.08838834764831845f;  // C^-0.5
#pragma unroll
    for (int nt = 0; nt < 4; nt++) {
        int nloc = wn * 32 + nt * 8 + 2 * tg;   // even, 0..126
        float2 bb = *(const float2*)(bias + bx * 128 + nloc);
#pragma unroll
        for (int mt = 0; mt < 2; mt++) {
            int row0 = by * 64 + wm * 32 + mt * 16 + g;
            float2 o0 = { acc[mt][nt][0] + bb.x, acc[mt][nt][1] + bb.y };
            float2 o1 = { acc[mt][nt][2] + bb.x, acc[mt][nt][3] + bb.y };
            if (bx == 0) {           // q, pre-scaled fp32
                o0.x *= QS; o0.y *= QS; o1.x *= QS; o1.y *= QS;
                *(float2*)(g_q + (size_t)row0 * 128 + nloc) = o0;
                *(float2*)(g_q + (size_t)(row0 + 8) * 128 + nloc) = o1;
            } else if (bx == 1) {    // k, bf16x2
                g_k[row0 * 64 + (nloc >> 1)]       = pack_bf16(o0.x, o0.y);
                g_k[(row0 + 8) * 64 + (nloc >> 1)] = pack_bf16(o1.x, o1.y);
            } else {                 // v, bf16x2
                g_v[row0 * 64 + (nloc >> 1)]       = pack_bf16(o0.x, o0.y);
                g_v[(row0 + 8) * 64 + (nloc >> 1)] = pack_bf16(o1.x, o1.y);
            }
        }
    }
}

// Kernel 4: proj GEMM (A = g_att fp32, B = proj_w, +bias +resid -> out)
__global__ void __launch_bounds__(256, 2)
gemm_proj(const float* __restrict__ Bw, const float* __restrict__ bias,
          const float* __restrict__ resid, float* __restrict__ outArg) {
    extern __shared__ uint32_t su[];
    uint32_t* As = su;
    uint32_t* Bs = su + A_U;

    int tid = threadIdx.x;
    int lane = tid & 31;
    int warp = tid >> 5;
    int wm = warp & 1;
    int wn = warp >> 1;
    int g = lane >> 2, tg = lane & 3;

    const float* Abase = g_att + (size_t)blockIdx.y * 64 * CC;
#pragma unroll
    for (int i = 0; i < 8; i++) {
        int id = tid + i * 256;
        int r = id >> 5, c4 = (id & 31) << 2;
        float4 v = *(const float4*)(Abase + (size_t)r * CC + c4);
        As[r * LDU + (c4 >> 1)]     = pack_bf16(v.x, v.y);
        As[r * LDU + (c4 >> 1) + 1] = pack_bf16(v.z, v.w);
    }
#pragma unroll
    for (int i = 0; i < 16; i++) {
        int id = tid + i * 256;
        int r = id >> 5, c4 = (id & 31) << 2;
        float4 v = *(const float4*)(Bw + (size_t)r * CC + c4);
        Bs[r * LDU + (c4 >> 1)]     = pack_bf16(v.x, v.y);
        Bs[r * LDU + (c4 >> 1) + 1] = pack_bf16(v.z, v.w);
    }
    __syncthreads();

    float acc[2][4][4];
#pragma unroll
    for (int i = 0; i < 2; i++)
#pragma unroll
        for (int j = 0; j < 4; j++)
#pragma unroll
            for (int e = 0; e < 4; e++) acc[i][j][e] = 0.f;

#pragma unroll
    for (int ks = 0; ks < 8; ks++) {
        int kb = ks * 8;
        uint32_t af[2][4], bf[4][2];
#pragma unroll
        for (int mt = 0; mt < 2; mt++) {
            int m = wm * 32 + mt * 16 + g;
            af[mt][0] = As[m * LDU + kb + tg];
            af[mt][1] = As[(m + 8) * LDU + kb + tg];
            af[mt][2] = As[m * LDU + kb + tg + 4];
            af[mt][3] = As[(m + 8) * LDU + kb + tg + 4];
        }
#pragma unroll
        for (int nt = 0; nt < 4; nt++) {
            int n = wn * 32 + nt * 8 + g;
            bf[nt][0] = Bs[n * LDU + kb + tg];
            bf[nt][1] = Bs[n * LDU + kb + tg + 4];
        }
#pragma unroll
        for (int mt = 0; mt < 2; mt++)
#pragma unroll
            for (int nt = 0; nt < 4; nt++)
                mma_bf16(acc[mt][nt], af[mt], bf[nt]);
    }

#pragma unroll
    for (int nt = 0; nt < 4; nt++) {
        int n = wn * 32 + nt * 8 + 2 * tg;
        float2 bb = *(const float2*)(bias + n);
#pragma unroll
        for (int mt = 0; mt < 2; mt++) {
            int row0 = blockIdx.y * 64 + wm * 32 + mt * 16 + g;
            float2 r0 = *(const float2*)(resid + (size_t)row0 * 128 + n);
            float2 r1 = *(const float2*)(resid + (size_t)(row0 + 8) * 128 + n);
            float2 o0 = { acc[mt][nt][0] + bb.x + r0.x, acc[mt][nt][1] + bb.y + r0.y };
            float2 o1 = { acc[mt][nt][2] + bb.x + r1.x, acc[mt][nt][3] + bb.y + r1.y };
            *(float2*)(outArg + (size_t)row0 * 128 + n) = o0;
            *(float2*)(outArg + (size_t)(row0 + 8) * 128 + n) = o1;
        }
    }
}

// ---------------------------------------------------------------------------
// Kernel 3: neighborhood attention. 8 positions/CTA (1t x 2h x 4w), union
// 3x4x6 = 72 k/v rows staged as bf16x2 (45 KB smem -> 5 CTAs/SM).
// ---------------------------------------------------------------------------
#define KPAD 66   // u32 per bf16 row (64 data + 2 pad)

__global__ void __launch_bounds__(256)
attn_kernel(const float* __restrict__ rpb) {
    extern __shared__ float sm[];
    float*    qsm   = sm;                               // 8*132 floats (16B aligned)
    uint32_t* ksm_u = (uint32_t*)(qsm + 8 * 132);       // 72*KPAD
    uint32_t* vsm_u = ksm_u + 72 * KPAD;                // 72*KPAD
    float*    sc    = (float*)(vsm_u + 72 * KPAD);      // 8*32
    float*    aw    = sc + 256;                         // 8*32
    int*      sl    = (int*)(aw + 256);                 // 8*32

    int tid = threadIdx.x, lane = tid & 31, warp = tid >> 5;
    int w0 = blockIdx.x * 4, h0 = blockIdx.y * 2, t = blockIdx.z;

    int st  = min(max(t  - 1, 0), TT - 3);
    int hlo = min(max(h0 - 1, 0), HH - 3);
    int wlo = min(max(w0 - 1, 0), WW - 3);

    int ph = h0 + (warp >> 2), pw = w0 + (warp & 3);
    int p  = (t * HH + ph) * WW + pw;

    if (lane < 27) {
        int dt = lane / 9, dh = (lane / 3) % 3, dw = lane % 3;
        int sh = min(max(ph - 1, 0), HH - 3);
        int sw = min(max(pw - 1, 0), WW - 3);
        int nt = st + dt, nh = sh + dh, nw = sw + dw;
        sl[warp * 32 + lane] = (dt * 4 + (nh - hlo)) * 6 + (nw - wlo);
        int bt = nt - t + 2, bh = nh - ph + 2, bw = nw - pw + 2;
        sc[warp * 32 + lane] = __ldg(&rpb[(bt * 5 + bh) * 5 + bw]);
    }

    // q (already scaled in qkv epilogue)
    *(float4*)(qsm + warp * 132 + lane * 4) =
        *(const float4*)(g_q + (size_t)p * 128 + lane * 4);

    // stage union k/v rows (bf16x2: 64 u32 per row, lane loads uint2)
    for (int rowid = warp; rowid < 72; rowid += 8) {
        int dt = rowid / 24, rrem = rowid % 24;
        int dh = rrem / 6, dw = rrem % 6;
        int nh = min(hlo + dh, HH - 1);
        int nw = min(wlo + dw, WW - 1);
        int np = ((st + dt) * HH + nh) * WW + nw;
        *(uint2*)(ksm_u + rowid * KPAD + lane * 2) = *(const uint2*)(g_k + np * 64 + lane * 2);
        *(uint2*)(vsm_u + rowid * KPAD + lane * 2) = *(const uint2*)(g_v + np * 64 + lane * 2);
    }
    __syncthreads();

    // scores: 27 dot-128 per warp (bf16 k -> fp32)
    {
        float4 q4 = *(const float4*)(qsm + warp * 132 + lane * 4);
#pragma unroll
        for (int n = 0; n < 27; n++) {
            int slot = sl[warp * 32 + n];
            uint2 kk = *(const uint2*)(ksm_u + slot * KPAD + lane * 2);
            float2 f0 = __bfloat1622float2(*(const __nv_bfloat162*)&kk.x);
            float2 f1 = __bfloat1622float2(*(const __nv_bfloat162*)&kk.y);
            float d = q4.x * f0.x + q4.y * f0.y + q4.z * f1.x + q4.w * f1.y;
#pragma unroll
            for (int o = 16; o; o >>= 1) d += __shfl_xor_sync(0xffffffffu, d, o);
            if (lane == 0) sc[warp * 32 + n] += d;
        }
    }
    __syncwarp();

    {
        float s = (lane < 27) ? sc[warp * 32 + lane] : -1e30f;
        float m = s;
#pragma unroll
        for (int o = 16; o; o >>= 1) m = fmaxf(m, __shfl_xor_sync(0xffffffffu, m, o));
        float e = (lane < 27) ? __expf(s - m) : 0.f;
        float den = e;
#pragma unroll
        for (int o = 16; o; o >>= 1) den += __shfl_xor_sync(0xffffffffu, den, o);
        aw[warp * 32 + lane] = e / den;
    }
    __syncwarp();

    {
        float4 acc = {0.f, 0.f, 0.f, 0.f};
#pragma unroll
        for (int n = 0; n < 27; n++) {
            float a = aw[warp * 32 + n];
            int slot = sl[warp * 32 + n];
            uint2 vv = *(const uint2*)(vsm_u + slot * KPAD + lane * 2);
            float2 f0 = __bfloat1622float2(*(const __nv_bfloat162*)&vv.x);
            float2 f1 = __bfloat1622float2(*(const __nv_bfloat162*)&vv.y);
            acc.x = fmaf(a, f0.x, acc.x);
            acc.y = fmaf(a, f0.y, acc.y);
            acc.z = fmaf(a, f1.x, acc.z);
            acc.w = fmaf(a, f1.y, acc.w);
        }
        *(float4*)(g_att + (size_t)p * 128 + lane * 4) = acc;
    }
}

static const int ATTN_SMEM = 8 * 132 * 4 + 72 * KPAD * 4 * 2 + 256 * 4 * 3;  // 45312 B
static_assert(8 * 132 * 4 + 72 * KPAD * 4 * 2 + 256 * 4 * 3 <= 227 * 1024, "attn smem");

// ---------------------------------------------------------------------------
extern "C" void kernel_launch(void* const* d_in, const int* in_sizes, int n_in,
                              void* d_out, int out_size) {
    const float* x      = (const float*)d_in[0];
    const float* gamma  = (const float*)d_in[1];
    const float* qkv_w  = (const float*)d_in[2];
    const float* qkv_b  = (const float*)d_in[3];
    const float* rpb    = (const float*)d_in[4];
    const float* proj_w = (const float*)d_in[5];
    const float* proj_b = (const float*)d_in[6];
    float* out = (float*)d_out;

    cudaFuncSetAttribute(attn_kernel, cudaFuncAttributeMaxDynamicSharedMemorySize, ATTN_SMEM);
    cudaFuncSetAttribute(gemm_qkv,  cudaFuncAttributeMaxDynamicSharedMemorySize, GSMEM);
    cudaFuncSetAttribute(gemm_proj, cudaFuncAttributeMaxDynamicSharedMemorySize, GSMEM);

    inv_kernel<<<(NS / 4 + 255) / 256, 256>>>(x);
    gemm_qkv<<<dim3(3, NS / 64), 256, GSMEM>>>(x, gamma, qkv_w, qkv_b);
    attn_kernel<<<dim3(WW / 4, HH / 2, TT), 256, ATTN_SMEM>>>(rpb);
    gemm_proj<<<dim3(1, NS / 64), 256, GSMEM>>>(proj_w, proj_b, x, out);
}